// round 1
// baseline (speedup 1.0000x reference)
#include <cuda_runtime.h>

// Problem constants (fixed by the reference): B=8, L=256, D=256, C=32
#define LQ    256
#define DIM   256
#define CH    32
#define BATCH 8
#define TI    16
#define TJ    32
#define XPAD  258   // x-tile row stride in smem (bank-conflict-free: 2*j+d distinct)

// Scratch: device globals (no cudaMalloc allowed anywhere).
__device__ float g_h[(size_t)BATCH * LQ * LQ * CH];     // 64 MB masked-relu hidden
__device__ float g_p[(size_t)BATCH * 49 * LQ * LQ];     // 98 MB per-tap projections

// ---- f32x2 packed-fp32 helpers (sm_100+ PTX) --------------------------------
__device__ __forceinline__ unsigned long long pk2(float lo, float hi) {
    unsigned long long r;
    asm("mov.b64 %0, {%1, %2};" : "=l"(r) : "f"(lo), "f"(hi));
    return r;
}
__device__ __forceinline__ void fma2(unsigned long long& a,
                                     unsigned long long x, unsigned long long y) {
    asm("fma.rn.f32x2 %0, %1, %2, %0;" : "+l"(a) : "l"(x), "l"(y));
}
__device__ __forceinline__ float2 up2(unsigned long long v) {
    float lo, hi;
    asm("mov.b64 {%0, %1}, %2;" : "=f"(lo), "=f"(hi) : "l"(v));
    return make_float2(lo, hi);
}

// ---- Kernel 1: fused pairwise-feature GEMM (K=512, N=32) + relu + mask ------
// block = (b, i-tile of 16, j-tile of 32); 256 threads; thread owns 2 pairs x 32 ch.
__global__ __launch_bounds__(256) void k_pair(const float* __restrict__ X,
                                              const int* __restrict__ plen_p,
                                              const float* __restrict__ W1,
                                              const float* __restrict__ b1) {
    extern __shared__ float smem[];
    float* sW  = smem;                 // 256 rows x 64 floats: [mul c0..31 | sub c0..31]
    float* sXi = sW + DIM * 64;        // TI x XPAD
    float* sXj = sXi + TI * XPAD;      // TJ x XPAD

    const int tid = threadIdx.x;
    const int b   = blockIdx.z;
    const int i0  = blockIdx.y * TI;
    const int j0  = blockIdx.x * TJ;
    const float* Xb = X + (size_t)b * LQ * DIM;

    // Stage W1 (re-laid per d-row) and x tiles into smem (coalesced).
    const float4* W4  = (const float4*)W1;      // [512][8] float4
    float4*       sW4 = (float4*)sW;
    #pragma unroll
    for (int t = tid; t < DIM * 16; t += 256) {
        int d = t >> 4, r = t & 15;
        sW4[t] = (r < 8) ? W4[d * 8 + r] : W4[(d + DIM) * 8 + (r - 8)];
    }
    for (int t = tid; t < TI * DIM; t += 256) {
        int r = t >> 8, c = t & 255;
        sXi[r * XPAD + c] = Xb[(size_t)(i0 + r) * DIM + c];
    }
    for (int t = tid; t < TJ * DIM; t += 256) {
        int r = t >> 8, c = t & 255;
        sXj[r * XPAD + c] = Xb[(size_t)(j0 + r) * DIM + c];
    }
    __syncthreads();

    const int jl = tid & 15;
    const int il = tid >> 4;

    unsigned long long acc0[16], acc1[16];     // channel pairs, pairs (il,jl),(il,jl+16)
    #pragma unroll
    for (int k = 0; k < 16; ++k) {
        unsigned long long bp = pk2(b1[2 * k], b1[2 * k + 1]);
        acc0[k] = bp; acc1[k] = bp;
    }

    const float* xi  = sXi + il * XPAD;
    const float* xj0 = sXj + jl * XPAD;
    const float* xj1 = sXj + (jl + 16) * XPAD;

    #pragma unroll 2
    for (int d = 0; d < DIM; ++d) {
        float a = xi[d], p = xj0[d], q = xj1[d];
        float m0 = a * p, s0 = fabsf(a - p);
        float m1 = a * q, s1 = fabsf(a - q);
        unsigned long long m0p = pk2(m0, m0), s0p = pk2(s0, s0);
        unsigned long long m1p = pk2(m1, m1), s1p = pk2(s1, s1);
        const ulonglong2* wr = (const ulonglong2*)(sW + (d << 6)); // broadcast reads
        #pragma unroll
        for (int k = 0; k < 8; ++k) {
            ulonglong2 wa = wr[k];        // mul-weights, channels 4k..4k+3
            ulonglong2 wb = wr[k + 8];    // sub-weights
            fma2(acc0[2 * k],     m0p, wa.x); fma2(acc0[2 * k + 1], m0p, wa.y);
            fma2(acc0[2 * k],     s0p, wb.x); fma2(acc0[2 * k + 1], s0p, wb.y);
            fma2(acc1[2 * k],     m1p, wa.x); fma2(acc1[2 * k + 1], m1p, wa.y);
            fma2(acc1[2 * k],     s1p, wb.x); fma2(acc1[2 * k + 1], s1p, wb.y);
        }
    }

    // Epilogue: relu + 2D mask, store h [b][i][j][c] contiguous in c.
    const int plen = plen_p[b];
    const int gi = i0 + il, gj0 = j0 + jl, gj1 = j0 + jl + 16;
    const bool v0 = (gi < plen) && (gj0 < plen);
    const bool v1 = (gi < plen) && (gj1 < plen);

    float o0[32], o1[32];
    #pragma unroll
    for (int k = 0; k < 16; ++k) {
        float2 f0 = up2(acc0[k]);
        o0[2 * k]     = v0 ? fmaxf(f0.x, 0.f) : 0.f;
        o0[2 * k + 1] = v0 ? fmaxf(f0.y, 0.f) : 0.f;
        float2 f1 = up2(acc1[k]);
        o1[2 * k]     = v1 ? fmaxf(f1.x, 0.f) : 0.f;
        o1[2 * k + 1] = v1 ? fmaxf(f1.y, 0.f) : 0.f;
    }
    float4* H0 = (float4*)(g_h + ((size_t)(b * LQ + gi) * LQ + gj0) * CH);
    float4* H1 = (float4*)(g_h + ((size_t)(b * LQ + gi) * LQ + gj1) * CH);
    #pragma unroll
    for (int q = 0; q < 8; ++q) {
        H0[q] = ((float4*)o0)[q];
        H1[q] = ((float4*)o1)[q];
    }
}

// ---- Kernel 2: per-tap projection P[b,t,i,j] = sum_c h[b,i,j,c] * W2[t,c] ---
__global__ __launch_bounds__(256) void k_proj(const float* __restrict__ W2) {
    __shared__ __align__(16) float sw[49 * CH];   // 6272 B, broadcast reads
    const int tid = threadIdx.x;
    for (int t = tid; t < 49 * CH; t += 256) sw[t] = W2[t];
    __syncthreads();

    const size_t row = (size_t)blockIdx.x * 256 + tid;   // < 524288
    const float* hp = g_h + row * CH;
    unsigned long long h2[16];
    #pragma unroll
    for (int q = 0; q < 8; ++q) {
        float4 v = ((const float4*)hp)[q];
        h2[2 * q]     = pk2(v.x, v.y);
        h2[2 * q + 1] = pk2(v.z, v.w);
    }
    const int b   = (int)(row >> 16);
    const int pos = (int)(row & 65535);
    float* Pb = g_p + (size_t)b * 49 * (LQ * LQ) + pos;
    #pragma unroll
    for (int t = 0; t < 49; ++t) {
        const ulonglong2* wv = (const ulonglong2*)(sw + t * CH);
        unsigned long long a0 = 0ull, a1 = 0ull;
        #pragma unroll
        for (int k = 0; k < 8; ++k) {
            ulonglong2 w = wv[k];
            fma2(a0, h2[2 * k],     w.x);
            fma2(a1, h2[2 * k + 1], w.y);
        }
        float2 fa = up2(a0), fb = up2(a1);
        Pb[(size_t)t * (LQ * LQ)] = (fa.x + fa.y) + (fb.x + fb.y);
    }
}

// ---- Kernel 3: gather-sum of 49 shifted P planes + bias + mask --------------
__global__ __launch_bounds__(256) void k_gather(const int* __restrict__ plen_p,
                                                const float* __restrict__ b2,
                                                float* __restrict__ out) {
    const int tid = threadIdx.x;
    const int j = blockIdx.x * 32 + (tid & 31);
    const int i = blockIdx.y * 8 + (tid >> 5);
    const int b = blockIdx.z;
    const int plen = plen_p[b];
    const float* Pb = g_p + (size_t)b * 49 * (LQ * LQ);

    float sum = 0.f;
    #pragma unroll
    for (int u = 0; u < 7; ++u) {
        int ii = i + u - 3;
        if (ii < 0 || ii >= LQ) continue;
        #pragma unroll
        for (int v = 0; v < 7; ++v) {
            int jj = j + v - 3;
            if (jj < 0 || jj >= LQ) continue;
            sum += Pb[(size_t)(u * 7 + v) * (LQ * LQ) + ii * LQ + jj];
        }
    }
    float r = (i < plen && j < plen) ? (sum + b2[0]) : 0.f;
    out[((size_t)b * LQ + i) * LQ + j] = r;
}

extern "C" void kernel_launch(void* const* d_in, const int* in_sizes, int n_in,
                              void* d_out, int out_size) {
    const float* enc  = (const float*)d_in[0];
    const int*   plen = (const int*)d_in[1];
    const float* W1   = (const float*)d_in[2];
    const float* b1   = (const float*)d_in[3];
    const float* W2   = (const float*)d_in[4];
    const float* b2   = (const float*)d_in[5];
    float* out = (float*)d_out;

    const int smem1 = (DIM * 64 + TI * XPAD + TJ * XPAD) * 4;  // 115072 B
    cudaFuncSetAttribute(k_pair, cudaFuncAttributeMaxDynamicSharedMemorySize, smem1);

    dim3 g1(LQ / TJ, LQ / TI, BATCH);          // (8, 16, 8) = 1024 blocks
    k_pair<<<g1, 256, smem1>>>(enc, plen, W1, b1);

    k_proj<<<(BATCH * LQ * LQ) / 256, 256>>>(W2);   // 2048 blocks

    dim3 g3(LQ / 32, LQ / 8, BATCH);           // (8, 32, 8)
    k_gather<<<g3, 256>>>(plen, b2, out);
}

// round 4
// speedup vs baseline: 1.0014x; 1.0014x over previous
#include <cuda_runtime.h>

// Problem constants (fixed by the reference): B=8, L=256, D=256, C=32
#define LQ    256
#define DIM   256
#define CH    32
#define BATCH 8
#define TI    16
#define TJ    32
#define XPAD  258   // x-tile row stride in smem (bank-conflict-free: 2*j+d distinct)

// Scratch: device globals (no cudaMalloc allowed anywhere).
__device__ float g_h[(size_t)BATCH * LQ * LQ * CH];     // 64 MB masked-relu hidden
__device__ float g_p[(size_t)BATCH * 49 * LQ * LQ];     // 98 MB per-tap projections

// ---- f32x2 packed-fp32 helpers (sm_100+ PTX) --------------------------------
__device__ __forceinline__ unsigned long long pk2(float lo, float hi) {
    unsigned long long r;
    asm("mov.b64 %0, {%1, %2};" : "=l"(r) : "f"(lo), "f"(hi));
    return r;
}
__device__ __forceinline__ void fma2(unsigned long long& a,
                                     unsigned long long x, unsigned long long y) {
    asm("fma.rn.f32x2 %0, %1, %2, %0;" : "+l"(a) : "l"(x), "l"(y));
}
__device__ __forceinline__ float2 up2(unsigned long long v) {
    float lo, hi;
    asm("mov.b64 {%0, %1}, %2;" : "=f"(lo), "=f"(hi) : "l"(v));
    return make_float2(lo, hi);
}

// ---- Kernel 1: fused pairwise-feature GEMM (K=512, N=32) + relu + mask ------
// block = (b, i-tile of 16, j-tile of 32); 256 threads; thread owns 2 pairs x 32 ch.
__global__ __launch_bounds__(256) void k_pair(const float* __restrict__ X,
                                              const int* __restrict__ plen_p,
                                              const float* __restrict__ W1,
                                              const float* __restrict__ b1) {
    extern __shared__ float smem[];
    float* sW  = smem;                 // 256 rows x 64 floats: [mul c0..31 | sub c0..31]
    float* sXi = sW + DIM * 64;        // TI x XPAD
    float* sXj = sXi + TI * XPAD;      // TJ x XPAD

    const int tid = threadIdx.x;
    const int b   = blockIdx.z;
    const int i0  = blockIdx.y * TI;
    const int j0  = blockIdx.x * TJ;
    const float* Xb = X + (size_t)b * LQ * DIM;

    // Stage W1 (re-laid per d-row) and x tiles into smem (coalesced).
    const float4* W4  = (const float4*)W1;      // [512][8] float4
    float4*       sW4 = (float4*)sW;
    #pragma unroll
    for (int t = tid; t < DIM * 16; t += 256) {
        int d = t >> 4, r = t & 15;
        sW4[t] = (r < 8) ? W4[d * 8 + r] : W4[(d + DIM) * 8 + (r - 8)];
    }
    for (int t = tid; t < TI * DIM; t += 256) {
        int r = t >> 8, c = t & 255;
        sXi[r * XPAD + c] = Xb[(size_t)(i0 + r) * DIM + c];
    }
    for (int t = tid; t < TJ * DIM; t += 256) {
        int r = t >> 8, c = t & 255;
        sXj[r * XPAD + c] = Xb[(size_t)(j0 + r) * DIM + c];
    }
    __syncthreads();

    const int jl = tid & 15;
    const int il = tid >> 4;

    unsigned long long acc0[16], acc1[16];     // channel pairs, pairs (il,jl),(il,jl+16)
    #pragma unroll
    for (int k = 0; k < 16; ++k) {
        unsigned long long bp = pk2(b1[2 * k], b1[2 * k + 1]);
        acc0[k] = bp; acc1[k] = bp;
    }

    const float* xi  = sXi + il * XPAD;
    const float* xj0 = sXj + jl * XPAD;
    const float* xj1 = sXj + (jl + 16) * XPAD;

    #pragma unroll 2
    for (int d = 0; d < DIM; ++d) {
        float a = xi[d], p = xj0[d], q = xj1[d];
        float m0 = a * p, s0 = fabsf(a - p);
        float m1 = a * q, s1 = fabsf(a - q);
        unsigned long long m0p = pk2(m0, m0), s0p = pk2(s0, s0);
        unsigned long long m1p = pk2(m1, m1), s1p = pk2(s1, s1);
        const ulonglong2* wr = (const ulonglong2*)(sW + (d << 6)); // broadcast reads
        #pragma unroll
        for (int k = 0; k < 8; ++k) {
            ulonglong2 wa = wr[k];        // mul-weights, channels 4k..4k+3
            ulonglong2 wb = wr[k + 8];    // sub-weights
            fma2(acc0[2 * k],     m0p, wa.x); fma2(acc0[2 * k + 1], m0p, wa.y);
            fma2(acc0[2 * k],     s0p, wb.x); fma2(acc0[2 * k + 1], s0p, wb.y);
            fma2(acc1[2 * k],     m1p, wa.x); fma2(acc1[2 * k + 1], m1p, wa.y);
            fma2(acc1[2 * k],     s1p, wb.x); fma2(acc1[2 * k + 1], s1p, wb.y);
        }
    }

    // Epilogue: relu + 2D mask, store h [b][i][j][c] contiguous in c.
    const int plen = plen_p[b];
    const int gi = i0 + il, gj0 = j0 + jl, gj1 = j0 + jl + 16;
    const bool v0 = (gi < plen) && (gj0 < plen);
    const bool v1 = (gi < plen) && (gj1 < plen);

    float o0[32], o1[32];
    #pragma unroll
    for (int k = 0; k < 16; ++k) {
        float2 f0 = up2(acc0[k]);
        o0[2 * k]     = v0 ? fmaxf(f0.x, 0.f) : 0.f;
        o0[2 * k + 1] = v0 ? fmaxf(f0.y, 0.f) : 0.f;
        float2 f1 = up2(acc1[k]);
        o1[2 * k]     = v1 ? fmaxf(f1.x, 0.f) : 0.f;
        o1[2 * k + 1] = v1 ? fmaxf(f1.y, 0.f) : 0.f;
    }
    float4* H0 = (float4*)(g_h + ((size_t)(b * LQ + gi) * LQ + gj0) * CH);
    float4* H1 = (float4*)(g_h + ((size_t)(b * LQ + gi) * LQ + gj1) * CH);
    #pragma unroll
    for (int q = 0; q < 8; ++q) {
        H0[q] = ((float4*)o0)[q];
        H1[q] = ((float4*)o1)[q];
    }
}

// ---- Kernel 2: per-tap projection P[b,t,i,j] = sum_c h[b,i,j,c] * W2[t,c] ---
__global__ __launch_bounds__(256) void k_proj(const float* __restrict__ W2) {
    __shared__ __align__(16) float sw[49 * CH];   // 6272 B, broadcast reads
    const int tid = threadIdx.x;
    for (int t = tid; t < 49 * CH; t += 256) sw[t] = W2[t];
    __syncthreads();

    const size_t row = (size_t)blockIdx.x * 256 + tid;   // < 524288
    const float* hp = g_h + row * CH;
    unsigned long long h2[16];
    #pragma unroll
    for (int q = 0; q < 8; ++q) {
        float4 v = ((const float4*)hp)[q];
        h2[2 * q]     = pk2(v.x, v.y);
        h2[2 * q + 1] = pk2(v.z, v.w);
    }
    const int b   = (int)(row >> 16);
    const int pos = (int)(row & 65535);
    float* Pb = g_p + (size_t)b * 49 * (LQ * LQ) + pos;
    #pragma unroll
    for (int t = 0; t < 49; ++t) {
        const ulonglong2* wv = (const ulonglong2*)(sw + t * CH);
        unsigned long long a0 = 0ull, a1 = 0ull;
        #pragma unroll
        for (int k = 0; k < 8; ++k) {
            ulonglong2 w = wv[k];
            fma2(a0, h2[2 * k],     w.x);
            fma2(a1, h2[2 * k + 1], w.y);
        }
        float2 fa = up2(a0), fb = up2(a1);
        Pb[(size_t)t * (LQ * LQ)] = (fa.x + fa.y) + (fb.x + fb.y);
    }
}

// ---- Kernel 3: gather-sum of 49 shifted P planes + bias + mask --------------
__global__ __launch_bounds__(256) void k_gather(const int* __restrict__ plen_p,
                                                const float* __restrict__ b2,
                                                float* __restrict__ out) {
    const int tid = threadIdx.x;
    const int j = blockIdx.x * 32 + (tid & 31);
    const int i = blockIdx.y * 8 + (tid >> 5);
    const int b = blockIdx.z;
    const int plen = plen_p[b];
    const float* Pb = g_p + (size_t)b * 49 * (LQ * LQ);

    float sum = 0.f;
    #pragma unroll
    for (int u = 0; u < 7; ++u) {
        int ii = i + u - 3;
        if (ii < 0 || ii >= LQ) continue;
        #pragma unroll
        for (int v = 0; v < 7; ++v) {
            int jj = j + v - 3;
            if (jj < 0 || jj >= LQ) continue;
            sum += Pb[(size_t)(u * 7 + v) * (LQ * LQ) + ii * LQ + jj];
        }
    }
    float r = (i < plen && j < plen) ? (sum + b2[0]) : 0.f;
    out[((size_t)b * LQ + i) * LQ + j] = r;
}

extern "C" void kernel_launch(void* const* d_in, const int* in_sizes, int n_in,
                              void* d_out, int out_size) {
    const float* enc  = (const float*)d_in[0];
    const int*   plen = (const int*)d_in[1];
    const float* W1   = (const float*)d_in[2];
    const float* b1   = (const float*)d_in[3];
    const float* W2   = (const float*)d_in[4];
    const float* b2   = (const float*)d_in[5];
    float* out = (float*)d_out;

    const int smem1 = (DIM * 64 + TI * XPAD + TJ * XPAD) * 4;  // 115072 B
    cudaFuncSetAttribute(k_pair, cudaFuncAttributeMaxDynamicSharedMemorySize, smem1);

    dim3 g1(LQ / TJ, LQ / TI, BATCH);          // (8, 16, 8) = 1024 blocks
    k_pair<<<g1, 256, smem1>>>(enc, plen, W1, b1);

    k_proj<<<(BATCH * LQ * LQ) / 256, 256>>>(W2);   // 2048 blocks

    dim3 g3(LQ / 32, LQ / 8, BATCH);           // (8, 32, 8)
    k_gather<<<g3, 256>>>(plen, b2, out);
}

// round 7
// speedup vs baseline: 1.9519x; 1.9492x over previous
#include <cuda_runtime.h>
#include <cstdint>

#define LQ    256
#define DIM   256
#define CH    32
#define BATCH 8
#define XSTR  260   // x-tile row stride (floats): bank = 4*tg+tq => conflict-free

// -------- scratch (device globals; no cudaMalloc allowed) -------------------
__device__ float g_h[(size_t)BATCH * LQ * LQ * CH];     // 64 MB hidden
__device__ float g_p[(size_t)BATCH * 49 * LQ * LQ];     // 98 MB per-tap proj

// -------- f32x2 helpers (k_proj) ---------------------------------------------
__device__ __forceinline__ unsigned long long pk2(float lo, float hi) {
    unsigned long long r;
    asm("mov.b64 %0, {%1, %2};" : "=l"(r) : "f"(lo), "f"(hi));
    return r;
}
__device__ __forceinline__ void fma2(unsigned long long& a,
                                     unsigned long long x, unsigned long long y) {
    asm("fma.rn.f32x2 %0, %1, %2, %0;" : "+l"(a) : "l"(x), "l"(y));
}
__device__ __forceinline__ float2 up2(unsigned long long v) {
    float lo, hi;
    asm("mov.b64 {%0, %1}, %2;" : "=f"(lo), "=f"(hi) : "l"(v));
    return make_float2(lo, hi);
}

// -------- tf32 mma helpers ----------------------------------------------------
__device__ __forceinline__ uint32_t tf32c(float v) {     // round-to-nearest tf32
    uint32_t u;
    asm("cvt.rna.tf32.f32 %0, %1;" : "=r"(u) : "f"(v));
    return u;
}
__device__ __forceinline__ void mma_tf32(float* d, const uint32_t* a, const uint32_t* b) {
    asm volatile(
        "mma.sync.aligned.m16n8k8.row.col.f32.tf32.tf32.f32 "
        "{%0,%1,%2,%3}, {%4,%5,%6,%7}, {%8,%9}, {%0,%1,%2,%3};"
        : "+f"(d[0]), "+f"(d[1]), "+f"(d[2]), "+f"(d[3])
        : "r"(a[0]), "r"(a[1]), "r"(a[2]), "r"(a[3]), "r"(b[0]), "r"(b[1]));
}

// smem layout (byte offsets into dynamic smem)
#define S_B1  0
#define S_XI  128
#define S_XJ  (S_XI + 16 * XSTR * 4)     // 16768
#define S_WF  (S_XJ + 32 * XSTR * 4)     // 50048
#define SMEM_SZ (S_WF + 16384 * 4)       // 115584

// ---- Kernel 1: pairwise-feature GEMM on tensor cores (mma.sync tf32) --------
// CTA: 512 thr (16 warps), tile = 16 i-rows x 32 j-cols = 512 pairs.
// Warp w owns i-row w (xi warp-uniform); M=32 pairs/warp = 2 mma A-frags.
// K = 512 (256 mul + 256 sub), N = 32 (4 n-frags).
__global__ __launch_bounds__(512, 1)
void k_pair(const float* __restrict__ X, const int* __restrict__ plen_p,
            const float* __restrict__ W1, const float* __restrict__ b1) {
    extern __shared__ char smem[];
    float* sB1 = (float*)(smem + S_B1);
    float* sXi = (float*)(smem + S_XI);
    float* sXj = (float*)(smem + S_XJ);
    float* sWf = (float*)(smem + S_WF);

    const int tid = threadIdx.x;
    const int w    = tid >> 5;          // warp id = local i row
    const int lane = tid & 31;
    const int tg = lane >> 2, tq = lane & 3;
    const int b = blockIdx.z, i0 = blockIdx.y * 16, j0 = blockIdx.x * 32;
    const float* Xb = X + (size_t)b * LQ * DIM;

    if (tid < 32) sB1[tid] = b1[tid];
    // stage xi (16 rows) / xj (32 rows), float4, padded stride
    for (int idx = tid; idx < 16 * 64; idx += 512) {
        int r = idx >> 6, q = idx & 63;
        *(float4*)(sXi + r * XSTR + q * 4) = ((const float4*)(Xb + (size_t)(i0 + r) * DIM))[q];
    }
    for (int idx = tid; idx < 32 * 64; idx += 512) {
        int r = idx >> 6, q = idx & 63;
        *(float4*)(sXj + r * XSTR + q * 4) = ((const float4*)(Xb + (size_t)(j0 + r) * DIM))[q];
    }
    // stage W1 in B-fragment order, tf32-rounded:
    // float index = kb*512 + h*256 + f*64 + t*2 + e  (kb:d-block, h:mul/sub, f:n-frag)
    // element: k = (t&3)+4e, n = f*8 + (t>>2), d = h*256 + kb*8 + k
    for (int idx = tid; idx < 16384; idx += 512) {
        int e = idx & 1, t = (idx >> 1) & 31, f = (idx >> 6) & 3;
        int h = (idx >> 8) & 1, kb = idx >> 9;
        int k = (t & 3) + 4 * e, n = f * 8 + (t >> 2);
        int d = h * 256 + kb * 8 + k;
        ((uint32_t*)sWf)[idx] = tf32c(W1[d * 32 + n]);
    }
    __syncthreads();

    float acc[2][4][4];
    #pragma unroll
    for (int a = 0; a < 2; ++a)
        #pragma unroll
        for (int f = 0; f < 4; ++f)
            #pragma unroll
            for (int e = 0; e < 4; ++e) acc[a][f][e] = 0.f;

    const float* xiw = sXi + w * XSTR;

    #pragma unroll 2
    for (int kb = 0; kb < 32; ++kb) {
        const int d0 = kb * 8;
        const float xi0 = xiw[d0 + tq];          // warp-uniform broadcast
        const float xi1 = xiw[d0 + tq + 4];
        float xa[4], xb_[4];                     // xj rows tg, tg+8, tg+16, tg+24
        #pragma unroll
        for (int a = 0; a < 4; ++a) {
            const float* xr = sXj + (tg + a * 8) * XSTR + d0;
            xa[a] = xr[tq]; xb_[a] = xr[tq + 4];
        }
        // build A fragments in-register (product/abs-diff rounded once to tf32)
        uint32_t Am[2][4], As[2][4];
        #pragma unroll
        for (int fr = 0; fr < 2; ++fr) {
            const int r0 = fr * 2, r1 = fr * 2 + 1;
            Am[fr][0] = tf32c(xi0 * xa[r0]);
            Am[fr][1] = tf32c(xi0 * xa[r1]);
            Am[fr][2] = tf32c(xi1 * xb_[r0]);
            Am[fr][3] = tf32c(xi1 * xb_[r1]);
            As[fr][0] = tf32c(fabsf(xi0 - xa[r0]));
            As[fr][1] = tf32c(fabsf(xi0 - xa[r1]));
            As[fr][2] = tf32c(fabsf(xi1 - xb_[r0]));
            As[fr][3] = tf32c(fabsf(xi1 - xb_[r1]));
        }
        // B fragments (LDS.64, conflict-free)
        const float2* wf = (const float2*)sWf + (size_t)kb * 256 + lane;
        uint32_t Bm[4][2], Bs[4][2];
        #pragma unroll
        for (int f = 0; f < 4; ++f) {
            float2 v0 = wf[f * 32];
            float2 v1 = wf[128 + f * 32];
            Bm[f][0] = __float_as_uint(v0.x); Bm[f][1] = __float_as_uint(v0.y);
            Bs[f][0] = __float_as_uint(v1.x); Bs[f][1] = __float_as_uint(v1.y);
        }
        #pragma unroll
        for (int fr = 0; fr < 2; ++fr)
            #pragma unroll
            for (int f = 0; f < 4; ++f) {
                mma_tf32(acc[fr][f], Am[fr], Bm[f]);
                mma_tf32(acc[fr][f], As[fr], Bs[f]);
            }
    }

    // epilogue: bias + relu + mask -> g_h[b][i][j][c]
    const int plen = __ldg(plen_p + b);
    const int gi = i0 + w;
    const bool vi = gi < plen;
    #pragma unroll
    for (int fr = 0; fr < 2; ++fr) {
        #pragma unroll
        for (int s = 0; s < 2; ++s) {
            const int gj = j0 + fr * 16 + tg + 8 * s;
            const bool v = vi && (gj < plen);
            float* Hrow = g_h + ((size_t)(b * LQ + gi) * LQ + gj) * CH;
            #pragma unroll
            for (int f = 0; f < 4; ++f) {
                const int ch = f * 8 + 2 * tq;
                float2 val;
                val.x = v ? fmaxf(acc[fr][f][2 * s]     + sB1[ch],     0.f) : 0.f;
                val.y = v ? fmaxf(acc[fr][f][2 * s + 1] + sB1[ch + 1], 0.f) : 0.f;
                *(float2*)(Hrow + ch) = val;
            }
        }
    }
}

// ---- Kernel 2: per-tap projection P[b,t,i,j] = sum_c h * W2[t,c] ------------
__global__ __launch_bounds__(256) void k_proj(const float* __restrict__ W2) {
    __shared__ __align__(16) float sw[49 * CH];
    const int tid = threadIdx.x;
    for (int t = tid; t < 49 * CH; t += 256) sw[t] = W2[t];
    __syncthreads();
    const size_t row = (size_t)blockIdx.x * 256 + tid;
    const float* hp = g_h + row * CH;
    unsigned long long h2[16];
    #pragma unroll
    for (int q = 0; q < 8; ++q) {
        float4 v = ((const float4*)hp)[q];
        h2[2*q] = pk2(v.x, v.y); h2[2*q+1] = pk2(v.z, v.w);
    }
    const int b = (int)(row >> 16), pos = (int)(row & 65535);
    float* Pb = g_p + (size_t)b * 49 * (LQ * LQ) + pos;
    #pragma unroll
    for (int t = 0; t < 49; ++t) {
        const ulonglong2* wv = (const ulonglong2*)(sw + t * CH);
        unsigned long long a0 = 0ull, a1 = 0ull;
        #pragma unroll
        for (int k = 0; k < 8; ++k) {
            ulonglong2 w = wv[k];
            fma2(a0, h2[2*k], w.x); fma2(a1, h2[2*k+1], w.y);
        }
        float2 fa = up2(a0), fb = up2(a1);
        Pb[(size_t)t * (LQ * LQ)] = (fa.x + fa.y) + (fb.x + fb.y);
    }
}

// ---- Kernel 3: gather-sum of 49 shifted P planes + bias + mask --------------
__global__ __launch_bounds__(256) void k_gather(const int* __restrict__ plen_p,
                                                const float* __restrict__ b2,
                                                float* __restrict__ out) {
    const int tid = threadIdx.x;
    const int j = blockIdx.x * 32 + (tid & 31);
    const int i = blockIdx.y * 8 + (tid >> 5);
    const int b = blockIdx.z;
    const int plen = plen_p[b];
    const float* Pb = g_p + (size_t)b * 49 * (LQ * LQ);
    float sum = 0.f;
    #pragma unroll
    for (int u = 0; u < 7; ++u) {
        int ii = i + u - 3;
        if (ii < 0 || ii >= LQ) continue;
        #pragma unroll
        for (int v = 0; v < 7; ++v) {
            int jj = j + v - 3;
            if (jj < 0 || jj >= LQ) continue;
            sum += Pb[(size_t)(u * 7 + v) * (LQ * LQ) + ii * LQ + jj];
        }
    }
    out[((size_t)b * LQ + i) * LQ + j] = (i < plen && j < plen) ? (sum + b2[0]) : 0.f;
}

extern "C" void kernel_launch(void* const* d_in, const int* in_sizes, int n_in,
                              void* d_out, int out_size) {
    const float* enc  = (const float*)d_in[0];
    const int*   plen = (const int*)d_in[1];
    const float* W1   = (const float*)d_in[2];
    const float* b1   = (const float*)d_in[3];
    const float* W2   = (const float*)d_in[4];
    const float* b2   = (const float*)d_in[5];
    float* out = (float*)d_out;

    cudaFuncSetAttribute(k_pair, cudaFuncAttributeMaxDynamicSharedMemorySize, SMEM_SZ);
    dim3 g1(LQ / 32, LQ / 16, BATCH);           // (8, 16, 8) = 1024 CTAs
    k_pair<<<g1, 512, SMEM_SZ>>>(enc, plen, W1, b1);

    k_proj<<<(BATCH * LQ * LQ) / 256, 256>>>(W2);

    dim3 g3(LQ / 32, LQ / 8, BATCH);
    k_gather<<<g3, 256>>>(plen, b2, out);
}

// round 8
// speedup vs baseline: 2.6054x; 1.3348x over previous
#include <cuda_runtime.h>
#include <cstdint>

#define LQ    256
#define DIM   256
#define CH    32
#define BATCH 8
#define XSTR  260   // x-tile row stride (floats): bank = 4*tg+tq => conflict-free

// -------- scratch (device globals; no cudaMalloc allowed) -------------------
__device__ float    g_h[(size_t)BATCH * LQ * LQ * CH];       // 64 MB hidden
__device__ float    g_q[(size_t)BATCH * 7 * LQ * LQ];        // 14.7 MB row-conv
__device__ uint32_t g_wf[16384];                             // W1 tf32 B-fragments

// -------- f32x2 helpers ------------------------------------------------------
__device__ __forceinline__ unsigned long long pk2(float lo, float hi) {
    unsigned long long r;
    asm("mov.b64 %0, {%1, %2};" : "=l"(r) : "f"(lo), "f"(hi));
    return r;
}
__device__ __forceinline__ void fma2(unsigned long long& a,
                                     unsigned long long x, unsigned long long y) {
    asm("fma.rn.f32x2 %0, %1, %2, %0;" : "+l"(a) : "l"(x), "l"(y));
}
__device__ __forceinline__ float2 up2(unsigned long long v) {
    float lo, hi;
    asm("mov.b64 {%0, %1}, %2;" : "=f"(lo), "=f"(hi) : "l"(v));
    return make_float2(lo, hi);
}

// -------- tf32 mma helpers ---------------------------------------------------
__device__ __forceinline__ uint32_t tf32c(float v) {     // round-to-nearest tf32
    uint32_t u;
    asm("cvt.rna.tf32.f32 %0, %1;" : "=r"(u) : "f"(v));
    return u;
}
__device__ __forceinline__ void mma_tf32(float* d, const uint32_t* a, const uint32_t* b) {
    asm volatile(
        "mma.sync.aligned.m16n8k8.row.col.f32.tf32.tf32.f32 "
        "{%0,%1,%2,%3}, {%4,%5,%6,%7}, {%8,%9}, {%0,%1,%2,%3};"
        : "+f"(d[0]), "+f"(d[1]), "+f"(d[2]), "+f"(d[3])
        : "r"(a[0]), "r"(a[1]), "r"(a[2]), "r"(a[3]), "r"(b[0]), "r"(b[1]));
}

// ---- Kernel 0: precompute W1 tf32 fragments into g_wf -----------------------
// float2 index (kb*256 + h*128 + f*32 + t); element e of pair:
//   k=(t&3)+4e, n=f*8+(t>>2), d=h*256+kb*8+k
__global__ __launch_bounds__(256) void k_prewf(const float* __restrict__ W1) {
    int idx = blockIdx.x * 256 + threadIdx.x;       // [0, 16384)
    int e = idx & 1, t = (idx >> 1) & 31, f = (idx >> 6) & 3;
    int h = (idx >> 8) & 1, kb = idx >> 9;
    int k = (t & 3) + 4 * e, n = f * 8 + (t >> 2);
    int d = h * 256 + kb * 8 + k;
    g_wf[idx] = tf32c(W1[d * 32 + n]);
}

// smem layout for k_pair (byte offsets)
#define S_B1  0
#define S_XI  128
#define S_XJ  (S_XI + 8 * XSTR * 4)      // 8448
#define SMEM1 (S_XJ + 32 * XSTR * 4)     // 41728

// ---- Kernel 1: pairwise-feature GEMM on tensor cores (mma.sync tf32) --------
// CTA: 256 thr (8 warps), tile = 8 i-rows x 32 j-cols. Warp w owns i-row w.
__global__ __launch_bounds__(256, 3)
void k_pair(const float* __restrict__ X, const int* __restrict__ plen_p,
            const float* __restrict__ b1) {
    extern __shared__ char smem[];
    float* sB1 = (float*)(smem + S_B1);
    float* sXi = (float*)(smem + S_XI);
    float* sXj = (float*)(smem + S_XJ);

    const int tid = threadIdx.x;
    const int w    = tid >> 5;          // warp id = local i row (0..7)
    const int lane = tid & 31;
    const int tg = lane >> 2, tq = lane & 3;
    const int b = blockIdx.z, i0 = blockIdx.y * 8, j0 = blockIdx.x * 32;
    const float* Xb = X + (size_t)b * LQ * DIM;

    if (tid < 32) sB1[tid] = b1[tid];
    for (int idx = tid; idx < 8 * 64; idx += 256) {
        int r = idx >> 6, q = idx & 63;
        *(float4*)(sXi + r * XSTR + q * 4) = ((const float4*)(Xb + (size_t)(i0 + r) * DIM))[q];
    }
    for (int idx = tid; idx < 32 * 64; idx += 256) {
        int r = idx >> 6, q = idx & 63;
        *(float4*)(sXj + r * XSTR + q * 4) = ((const float4*)(Xb + (size_t)(j0 + r) * DIM))[q];
    }
    __syncthreads();

    float acc[2][4][4];
    #pragma unroll
    for (int a = 0; a < 2; ++a)
        #pragma unroll
        for (int f = 0; f < 4; ++f)
            #pragma unroll
            for (int e = 0; e < 4; ++e) acc[a][f][e] = 0.f;

    const float* xiw = sXi + w * XSTR;
    const float2* wfb = (const float2*)g_wf + lane;

    #pragma unroll 2
    for (int kb = 0; kb < 32; ++kb) {
        const int d0 = kb * 8;
        // B fragments from global (L1-resident after first wave)
        const float2* wf = wfb + (size_t)kb * 256;
        uint32_t Bm[4][2], Bs[4][2];
        #pragma unroll
        for (int f = 0; f < 4; ++f) {
            float2 v0 = __ldg(wf + f * 32);
            float2 v1 = __ldg(wf + 128 + f * 32);
            Bm[f][0] = __float_as_uint(v0.x); Bm[f][1] = __float_as_uint(v0.y);
            Bs[f][0] = __float_as_uint(v1.x); Bs[f][1] = __float_as_uint(v1.y);
        }
        const float xi0 = xiw[d0 + tq];          // warp-uniform broadcast
        const float xi1 = xiw[d0 + tq + 4];
        float xa[4], xb_[4];                     // xj rows tg, tg+8, tg+16, tg+24
        #pragma unroll
        for (int a = 0; a < 4; ++a) {
            const float* xr = sXj + (tg + a * 8) * XSTR + d0;
            xa[a] = xr[tq]; xb_[a] = xr[tq + 4];
        }
        uint32_t Am[2][4], As[2][4];
        #pragma unroll
        for (int fr = 0; fr < 2; ++fr) {
            const int r0 = fr * 2, r1 = fr * 2 + 1;
            Am[fr][0] = tf32c(xi0 * xa[r0]);
            Am[fr][1] = tf32c(xi0 * xa[r1]);
            Am[fr][2] = tf32c(xi1 * xb_[r0]);
            Am[fr][3] = tf32c(xi1 * xb_[r1]);
            As[fr][0] = tf32c(fabsf(xi0 - xa[r0]));
            As[fr][1] = tf32c(fabsf(xi0 - xa[r1]));
            As[fr][2] = tf32c(fabsf(xi1 - xb_[r0]));
            As[fr][3] = tf32c(fabsf(xi1 - xb_[r1]));
        }
        #pragma unroll
        for (int fr = 0; fr < 2; ++fr)
            #pragma unroll
            for (int f = 0; f < 4; ++f) {
                mma_tf32(acc[fr][f], Am[fr], Bm[f]);
                mma_tf32(acc[fr][f], As[fr], Bs[f]);
            }
    }

    // epilogue: bias + relu + mask -> g_h[b][i][j][c]
    const int plen = __ldg(plen_p + b);
    const int gi = i0 + w;
    const bool vi = gi < plen;
    #pragma unroll
    for (int fr = 0; fr < 2; ++fr) {
        #pragma unroll
        for (int s = 0; s < 2; ++s) {
            const int gj = j0 + fr * 16 + tg + 8 * s;
            const bool v = vi && (gj < plen);
            float* Hrow = g_h + ((size_t)(b * LQ + gi) * LQ + gj) * CH;
            #pragma unroll
            for (int f = 0; f < 4; ++f) {
                const int ch = f * 8 + 2 * tq;
                float2 val;
                val.x = v ? fmaxf(acc[fr][f][2 * s]     + sB1[ch],     0.f) : 0.f;
                val.y = v ? fmaxf(acc[fr][f][2 * s + 1] + sB1[ch + 1], 0.f) : 0.f;
                *(float2*)(Hrow + ch) = val;
            }
        }
    }
}

// ---- Kernel 2: row conv  Q[b,u,i,j] = sum_{v,c} h[b,i,j+v-3,c] * W2[u,v,c] --
// CTA = one (b, i) row; 256 threads = j. h row + halo staged in smem.
#define HSTR 36                             // floats per pixel (32 + 4 pad)
__global__ __launch_bounds__(256) void k_rowconv(const float* __restrict__ W2) {
    __shared__ __align__(16) float sH[262 * HSTR];   // 37.7 KB
    __shared__ __align__(16) float sW2[49 * CH];     // 6.3 KB
    const int tid = threadIdx.x;
    const int i = blockIdx.x, b = blockIdx.y;

    for (int t = tid; t < 49 * CH; t += 256) sW2[t] = W2[t];
    const float* Hrow = g_h + ((size_t)(b * LQ + i) * LQ) * CH;
    for (int idx = tid; idx < 262 * 8; idx += 256) {
        int p = idx >> 3, q = idx & 7;                 // pixel p = gj + 3
        int gj = p - 3;
        float4 v = (gj >= 0 && gj < LQ) ? ((const float4*)(Hrow + (size_t)gj * CH))[q]
                                        : make_float4(0.f, 0.f, 0.f, 0.f);
        *(float4*)(sH + p * HSTR + q * 4) = v;
    }
    __syncthreads();

    const int j = tid;
    unsigned long long acc2[7][2];
    #pragma unroll
    for (int u = 0; u < 7; ++u) { acc2[u][0] = 0ull; acc2[u][1] = 0ull; }

    #pragma unroll
    for (int v = 0; v < 7; ++v) {
        const float* hp = sH + (j + v) * HSTR;         // pixel j+v-3
        unsigned long long h2[16];
        #pragma unroll
        for (int q = 0; q < 8; ++q) {
            float4 hv = *(const float4*)(hp + q * 4);
            h2[2*q] = pk2(hv.x, hv.y); h2[2*q+1] = pk2(hv.z, hv.w);
        }
        #pragma unroll
        for (int u = 0; u < 7; ++u) {
            const ulonglong2* wv = (const ulonglong2*)(sW2 + (u * 7 + v) * CH);
            #pragma unroll
            for (int k = 0; k < 8; ++k) {
                ulonglong2 wq = wv[k];
                fma2(acc2[u][0], h2[2*k],   wq.x);
                fma2(acc2[u][1], h2[2*k+1], wq.y);
            }
        }
    }
    float* Qb = g_q + (size_t)b * 7 * (LQ * LQ) + (size_t)i * LQ + j;
    #pragma unroll
    for (int u = 0; u < 7; ++u) {
        float2 fa = up2(acc2[u][0]), fb = up2(acc2[u][1]);
        Qb[(size_t)u * (LQ * LQ)] = (fa.x + fa.y) + (fb.x + fb.y);
    }
}

// ---- Kernel 3: col gather  out[b,i,j] = mask * (b2 + sum_u Q[b,u,i+u-3,j]) --
__global__ __launch_bounds__(256) void k_colgather(const int* __restrict__ plen_p,
                                                   const float* __restrict__ b2,
                                                   float* __restrict__ out) {
    const int j = threadIdx.x;
    const int i = blockIdx.x, b = blockIdx.y;
    const int plen = plen_p[b];
    const float* Qb = g_q + (size_t)b * 7 * (LQ * LQ) + j;
    float sum = 0.f;
    #pragma unroll
    for (int u = 0; u < 7; ++u) {
        int ii = i + u - 3;
        if (ii >= 0 && ii < LQ)
            sum += Qb[(size_t)u * (LQ * LQ) + (size_t)ii * LQ];
    }
    out[((size_t)b * LQ + i) * LQ + j] =
        (i < plen && j < plen) ? (sum + b2[0]) : 0.f;
}

extern "C" void kernel_launch(void* const* d_in, const int* in_sizes, int n_in,
                              void* d_out, int out_size) {
    const float* enc  = (const float*)d_in[0];
    const int*   plen = (const int*)d_in[1];
    const float* W1   = (const float*)d_in[2];
    const float* b1   = (const float*)d_in[3];
    const float* W2   = (const float*)d_in[4];
    const float* b2   = (const float*)d_in[5];
    float* out = (float*)d_out;

    k_prewf<<<64, 256>>>(W1);

    cudaFuncSetAttribute(k_pair, cudaFuncAttributeMaxDynamicSharedMemorySize, SMEM1);
    dim3 g1(LQ / 32, LQ / 8, BATCH);            // (8, 32, 8) = 2048 CTAs
    k_pair<<<g1, 256, SMEM1>>>(enc, plen, b1);

    dim3 g2(LQ, BATCH);                         // (256, 8) = 2048 CTAs
    k_rowconv<<<g2, 256>>>(W2);

    dim3 g3(LQ, BATCH);
    k_colgather<<<g3, 256>>>(plen, b2, out);
}

// round 12
// speedup vs baseline: 3.2080x; 1.2313x over previous
#include <cuda_runtime.h>
#include <cstdint>

#define LQ    256
#define DIM   256
#define CH    32
#define BATCH 8
#define XSTR  260   // x-tile row stride (floats): bank = 4*tg+tq => conflict-free

// -------- scratch (device globals; no cudaMalloc allowed) -------------------
__device__ float    g_h[(size_t)BATCH * LQ * LQ * CH];       // 64 MB hidden
__device__ float    g_q[(size_t)BATCH * 7 * LQ * LQ];        // 14.7 MB row-conv
__device__ uint32_t g_wf[16384];                             // W1 tf32 B-fragments

// -------- f32x2 helpers ------------------------------------------------------
__device__ __forceinline__ unsigned long long pk2(float lo, float hi) {
    unsigned long long r;
    asm("mov.b64 %0, {%1, %2};" : "=l"(r) : "f"(lo), "f"(hi));
    return r;
}
__device__ __forceinline__ void fma2(unsigned long long& a,
                                     unsigned long long x, unsigned long long y) {
    asm("fma.rn.f32x2 %0, %1, %2, %0;" : "+l"(a) : "l"(x), "l"(y));
}
__device__ __forceinline__ float2 up2(unsigned long long v) {
    float lo, hi;
    asm("mov.b64 {%0, %1}, %2;" : "=f"(lo), "=f"(hi) : "l"(v));
    return make_float2(lo, hi);
}

// -------- tf32 mma helpers ---------------------------------------------------
__device__ __forceinline__ uint32_t tf32c(float v) {     // round-to-nearest tf32
    uint32_t u;
    asm("cvt.rna.tf32.f32 %0, %1;" : "=r"(u) : "f"(v));
    return u;
}
__device__ __forceinline__ void mma_tf32(float* d, const uint32_t* a, const uint32_t* b) {
    asm volatile(
        "mma.sync.aligned.m16n8k8.row.col.f32.tf32.tf32.f32 "
        "{%0,%1,%2,%3}, {%4,%5,%6,%7}, {%8,%9}, {%0,%1,%2,%3};"
        : "+f"(d[0]), "+f"(d[1]), "+f"(d[2]), "+f"(d[3])
        : "r"(a[0]), "r"(a[1]), "r"(a[2]), "r"(a[3]), "r"(b[0]), "r"(b[1]));
}

// ---- Kernel 0: precompute W1 tf32 fragments into g_wf -----------------------
__global__ __launch_bounds__(256) void k_prewf(const float* __restrict__ W1) {
    int idx = blockIdx.x * 256 + threadIdx.x;       // [0, 16384)
    int e = idx & 1, t = (idx >> 1) & 31, f = (idx >> 6) & 3;
    int h = (idx >> 8) & 1, kb = idx >> 9;
    int k = (t & 3) + 4 * e, n = f * 8 + (t >> 2);
    int d = h * 256 + kb * 8 + k;
    g_wf[idx] = tf32c(W1[d * 32 + n]);
}

// smem layout for k_pair (byte offsets)
#define S_B1  0
#define S_XI  128
#define S_XJ  (S_XI + 8 * XSTR * 4)      // 8448
#define SMEM1 (S_XJ + 32 * XSTR * 4)     // 41728
#define NKEEP 144                         // upper-triangle 8x32 blocks per batch

// ---- Kernel 1: symmetric pairwise-feature GEMM (mma.sync tf32) --------------
// h[b,i,j,:] == h[b,j,i,:] exactly; compute only blocks with ib <= 4*jb+3 and
// mirror-write the transpose. CTA: 256 thr (8 warps), tile 8 i x 32 j.
__global__ __launch_bounds__(256, 3)
void k_pair(const float* __restrict__ X, const int* __restrict__ plen_p,
            const float* __restrict__ b1) {
    extern __shared__ char smem[];
    float* sB1 = (float*)(smem + S_B1);
    float* sXi = (float*)(smem + S_XI);
    float* sXj = (float*)(smem + S_XJ);

    const int tid = threadIdx.x;
    const int w    = tid >> 5;
    const int lane = tid & 31;
    const int tg = lane >> 2, tq = lane & 3;
    const int b = blockIdx.z;

    // kept-block index -> (ib, jb): block count up to jb is 2*jb^2+2*jb,
    // blocks for column-group jb are ib in [0, 4jb+4).
    const int idx = blockIdx.x;
    int jb = (int)floorf((sqrtf((float)(4 * idx) + 9.0f) - 3.0f) * 0.5f);
    while (2 * (jb + 1) * (jb + 1) + 2 * (jb + 1) <= idx) ++jb;   // fp-safety
    while (2 * jb * jb + 2 * jb > idx) --jb;
    const int ib = idx - (2 * jb * jb + 2 * jb);
    const int i0 = ib * 8, j0 = jb * 32;
    const float* Xb = X + (size_t)b * LQ * DIM;

    if (tid < 32) sB1[tid] = b1[tid];
    for (int t = tid; t < 8 * 64; t += 256) {
        int r = t >> 6, q = t & 63;
        *(float4*)(sXi + r * XSTR + q * 4) = ((const float4*)(Xb + (size_t)(i0 + r) * DIM))[q];
    }
    for (int t = tid; t < 32 * 64; t += 256) {
        int r = t >> 6, q = t & 63;
        *(float4*)(sXj + r * XSTR + q * 4) = ((const float4*)(Xb + (size_t)(j0 + r) * DIM))[q];
    }
    __syncthreads();

    float acc[2][4][4];
    #pragma unroll
    for (int a = 0; a < 2; ++a)
        #pragma unroll
        for (int f = 0; f < 4; ++f)
            #pragma unroll
            for (int e = 0; e < 4; ++e) acc[a][f][e] = 0.f;

    const float* xiw = sXi + w * XSTR;
    const float2* wfb = (const float2*)g_wf + lane;

    #pragma unroll 2
    for (int kb = 0; kb < 32; ++kb) {
        const int d0 = kb * 8;
        const float2* wf = wfb + (size_t)kb * 256;
        uint32_t Bm[4][2], Bs[4][2];
        #pragma unroll
        for (int f = 0; f < 4; ++f) {
            float2 v0 = __ldg(wf + f * 32);
            float2 v1 = __ldg(wf + 128 + f * 32);
            Bm[f][0] = __float_as_uint(v0.x); Bm[f][1] = __float_as_uint(v0.y);
            Bs[f][0] = __float_as_uint(v1.x); Bs[f][1] = __float_as_uint(v1.y);
        }
        const float xi0 = xiw[d0 + tq];
        const float xi1 = xiw[d0 + tq + 4];
        float xa[4], xb_[4];
        #pragma unroll
        for (int a = 0; a < 4; ++a) {
            const float* xr = sXj + (tg + a * 8) * XSTR + d0;
            xa[a] = xr[tq]; xb_[a] = xr[tq + 4];
        }
        uint32_t Am[2][4], As[2][4];
        #pragma unroll
        for (int fr = 0; fr < 2; ++fr) {
            const int r0 = fr * 2, r1 = fr * 2 + 1;
            Am[fr][0] = tf32c(xi0 * xa[r0]);
            Am[fr][1] = tf32c(xi0 * xa[r1]);
            Am[fr][2] = tf32c(xi1 * xb_[r0]);
            Am[fr][3] = tf32c(xi1 * xb_[r1]);
            As[fr][0] = tf32c(fabsf(xi0 - xa[r0]));
            As[fr][1] = tf32c(fabsf(xi0 - xa[r1]));
            As[fr][2] = tf32c(fabsf(xi1 - xb_[r0]));
            As[fr][3] = tf32c(fabsf(xi1 - xb_[r1]));
        }
        #pragma unroll
        for (int fr = 0; fr < 2; ++fr)
            #pragma unroll
            for (int f = 0; f < 4; ++f) {
                mma_tf32(acc[fr][f], Am[fr], Bm[f]);
                mma_tf32(acc[fr][f], As[fr], Bs[f]);
            }
    }

    // epilogue: bias + relu + mask -> g_h[b][i][j][:]  AND mirror g_h[b][j][i][:]
    const int plen = __ldg(plen_p + b);
    const int gi = i0 + w;
    const bool vi = gi < plen;
    #pragma unroll
    for (int fr = 0; fr < 2; ++fr) {
        #pragma unroll
        for (int s = 0; s < 2; ++s) {
            const int gj = j0 + fr * 16 + tg + 8 * s;
            const bool v = vi && (gj < plen);
            float* Hrow = g_h + ((size_t)(b * LQ + gi) * LQ + gj) * CH;
            float* Hcol = g_h + ((size_t)(b * LQ + gj) * LQ + gi) * CH;
            #pragma unroll
            for (int f = 0; f < 4; ++f) {
                const int ch = f * 8 + 2 * tq;
                float2 val;
                val.x = v ? fmaxf(acc[fr][f][2 * s]     + sB1[ch],     0.f) : 0.f;
                val.y = v ? fmaxf(acc[fr][f][2 * s + 1] + sB1[ch + 1], 0.f) : 0.f;
                *(float2*)(Hrow + ch) = val;
                *(float2*)(Hcol + ch) = val;
            }
        }
    }
}

// ---- Kernel 2: row conv  Q[b,u,i,j] = sum_{v,c} h[b,i,j+v-3,c] * W2[u,v,c] --
#define HSTR 36
__global__ __launch_bounds__(256) void k_rowconv(const float* __restrict__ W2) {
    __shared__ __align__(16) float sH[262 * HSTR];   // 37.7 KB
    __shared__ __align__(16) float sW2[49 * CH];     // 6.3 KB
    const int tid = threadIdx.x;
    const int i = blockIdx.x, b = blockIdx.y;

    for (int t = tid; t < 49 * CH; t += 256) sW2[t] = W2[t];
    const float* Hrow = g_h + ((size_t)(b * LQ + i) * LQ) * CH;
    for (int idx = tid; idx < 262 * 8; idx += 256) {
        int p = idx >> 3, q = idx & 7;                 // pixel p = gj + 3
        int gj = p - 3;
        float4 v = (gj >= 0 && gj < LQ) ? ((const float4*)(Hrow + (size_t)gj * CH))[q]
                                        : make_float4(0.f, 0.f, 0.f, 0.f);
        *(float4*)(sH + p * HSTR + q * 4) = v;
    }
    __syncthreads();

    const int j = tid;
    unsigned long long acc2[7][2];
    #pragma unroll
    for (int u = 0; u < 7; ++u) { acc2[u][0] = 0ull; acc2[u][1] = 0ull; }

    #pragma unroll
    for (int v = 0; v < 7; ++v) {
        const float* hp = sH + (j + v) * HSTR;
        unsigned long long h2[16];
        #pragma unroll
        for (int q = 0; q < 8; ++q) {
            float4 hv = *(const float4*)(hp + q * 4);
            h2[2*q] = pk2(hv.x, hv.y); h2[2*q+1] = pk2(hv.z, hv.w);
        }
        #pragma unroll
        for (int u = 0; u < 7; ++u) {
            const ulonglong2* wv = (const ulonglong2*)(sW2 + (u * 7 + v) * CH);
            #pragma unroll
            for (int k = 0; k < 8; ++k) {
                ulonglong2 wq = wv[k];
                fma2(acc2[u][0], h2[2*k],   wq.x);
                fma2(acc2[u][1], h2[2*k+1], wq.y);
            }
        }
    }
    float* Qb = g_q + (size_t)b * 7 * (LQ * LQ) + (size_t)i * LQ + j;
    #pragma unroll
    for (int u = 0; u < 7; ++u) {
        float2 fa = up2(acc2[u][0]), fb = up2(acc2[u][1]);
        Qb[(size_t)u * (LQ * LQ)] = (fa.x + fa.y) + (fb.x + fb.y);
    }
}

// ---- Kernel 3: col gather  out[b,i,j] = mask * (b2 + sum_u Q[b,u,i+u-3,j]) --
__global__ __launch_bounds__(256) void k_colgather(const int* __restrict__ plen_p,
                                                   const float* __restrict__ b2,
                                                   float* __restrict__ out) {
    const int j = threadIdx.x;
    const int i = blockIdx.x, b = blockIdx.y;
    const int plen = plen_p[b];
    const float* Qb = g_q + (size_t)b * 7 * (LQ * LQ) + j;
    float sum = 0.f;
    #pragma unroll
    for (int u = 0; u < 7; ++u) {
        int ii = i + u - 3;
        if (ii >= 0 && ii < LQ)
            sum += Qb[(size_t)u * (LQ * LQ) + (size_t)ii * LQ];
    }
    out[((size_t)b * LQ + i) * LQ + j] =
        (i < plen && j < plen) ? (sum + b2[0]) : 0.f;
}

extern "C" void kernel_launch(void* const* d_in, const int* in_sizes, int n_in,
                              void* d_out, int out_size) {
    const float* enc  = (const float*)d_in[0];
    const int*   plen = (const int*)d_in[1];
    const float* W1   = (const float*)d_in[2];
    const float* b1   = (const float*)d_in[3];
    const float* W2   = (const float*)d_in[4];
    const float* b2   = (const float*)d_in[5];
    float* out = (float*)d_out;

    k_prewf<<<64, 256>>>(W1);

    cudaFuncSetAttribute(k_pair, cudaFuncAttributeMaxDynamicSharedMemorySize, SMEM1);
    dim3 g1(NKEEP, 1, BATCH);                   // 144 upper-tri blocks x 8 batches
    k_pair<<<g1, 256, SMEM1>>>(enc, plen, b1);

    dim3 g2(LQ, BATCH);
    k_rowconv<<<g2, 256>>>(W2);

    dim3 g3(LQ, BATCH);
    k_colgather<<<g3, 256>>>(plen, b2, out);
}

// round 14
// speedup vs baseline: 3.9711x; 1.2379x over previous
#include <cuda_runtime.h>
#include <cstdint>

#define LQ    256
#define DIM   256
#define CH    32
#define BATCH 8
#define XSTR  260   // x-tile row stride (floats): bank = 4*tg+tq => conflict-free

// -------- scratch (device globals; no cudaMalloc allowed) -------------------
__device__ float    g_h[(size_t)BATCH * LQ * LQ * CH];       // 64 MB hidden
__device__ float    g_q[(size_t)BATCH * 7 * LQ * LQ];        // 14.7 MB row-conv
__device__ uint32_t g_wf[16384];                             // W1 tf32 B-fragments

// -------- f32x2 helpers ------------------------------------------------------
__device__ __forceinline__ unsigned long long pk2(float lo, float hi) {
    unsigned long long r;
    asm("mov.b64 %0, {%1, %2};" : "=l"(r) : "f"(lo), "f"(hi));
    return r;
}
__device__ __forceinline__ void fma2(unsigned long long& a,
                                     unsigned long long x, unsigned long long y) {
    asm("fma.rn.f32x2 %0, %1, %2, %0;" : "+l"(a) : "l"(x), "l"(y));
}
__device__ __forceinline__ float2 up2(unsigned long long v) {
    float lo, hi;
    asm("mov.b64 {%0, %1}, %2;" : "=f"(lo), "=f"(hi) : "l"(v));
    return make_float2(lo, hi);
}

// -------- tf32 mma helpers ---------------------------------------------------
__device__ __forceinline__ uint32_t tf32c(float v) {     // round-to-nearest tf32
    uint32_t u;
    asm("cvt.rna.tf32.f32 %0, %1;" : "=r"(u) : "f"(v));
    return u;
}
__device__ __forceinline__ void mma_tf32(float* d, const uint32_t* a, const uint32_t* b) {
    asm volatile(
        "mma.sync.aligned.m16n8k8.row.col.f32.tf32.tf32.f32 "
        "{%0,%1,%2,%3}, {%4,%5,%6,%7}, {%8,%9}, {%0,%1,%2,%3};"
        : "+f"(d[0]), "+f"(d[1]), "+f"(d[2]), "+f"(d[3])
        : "r"(a[0]), "r"(a[1]), "r"(a[2]), "r"(a[3]), "r"(b[0]), "r"(b[1]));
}

// ---- Kernel 0: precompute W1 tf32 fragments into g_wf -----------------------
__global__ __launch_bounds__(256) void k_prewf(const float* __restrict__ W1) {
    int idx = blockIdx.x * 256 + threadIdx.x;       // [0, 16384)
    int e = idx & 1, t = (idx >> 1) & 31, f = (idx >> 6) & 3;
    int h = (idx >> 8) & 1, kb = idx >> 9;
    int k = (t & 3) + 4 * e, n = f * 8 + (t >> 2);
    int d = h * 256 + kb * 8 + k;
    g_wf[idx] = tf32c(W1[d * 32 + n]);
}

// smem layout for k_pair (byte offsets)
#define S_B1  0
#define S_XI  128
#define S_XJ  (S_XI + 8 * XSTR * 4)      // 8448
#define SMEM1 (S_XJ + 32 * XSTR * 4)     // 41728
#define NKEEP 144                         // upper-triangle 8x32 blocks per batch

// ---- Kernel 1: symmetric pairwise-feature GEMM (mma.sync tf32) --------------
// h[b,i,j,:] == h[b,j,i,:] exactly; compute only blocks with ib <= 4*jb+3 and
// mirror-write the transpose. Fully-masked tiles skip the MMA loop entirely.
__global__ __launch_bounds__(256, 3)
void k_pair(const float* __restrict__ X, const int* __restrict__ plen_p,
            const float* __restrict__ b1) {
    extern __shared__ char smem[];
    float* sB1 = (float*)(smem + S_B1);
    float* sXi = (float*)(smem + S_XI);
    float* sXj = (float*)(smem + S_XJ);

    const int tid = threadIdx.x;
    const int w    = tid >> 5;
    const int lane = tid & 31;
    const int tg = lane >> 2, tq = lane & 3;
    const int b = blockIdx.z;

    // kept-block index -> (ib, jb): block count up to jb is 2*jb^2+2*jb,
    // blocks for column-group jb are ib in [0, 4jb+4).
    const int idx = blockIdx.x;
    int jb = (int)floorf((sqrtf((float)(4 * idx) + 9.0f) - 3.0f) * 0.5f);
    while (2 * (jb + 1) * (jb + 1) + 2 * (jb + 1) <= idx) ++jb;   // fp-safety
    while (2 * jb * jb + 2 * jb > idx) --jb;
    const int ib = idx - (2 * jb * jb + 2 * jb);
    const int i0 = ib * 8, j0 = jb * 32;
    const float* Xb = X + (size_t)b * LQ * DIM;
    const int plen = __ldg(plen_p + b);
    const bool live = (i0 < plen) && (j0 < plen);   // any unmasked cell in tile?

    float acc[2][4][4];
    #pragma unroll
    for (int a = 0; a < 2; ++a)
        #pragma unroll
        for (int f = 0; f < 4; ++f)
            #pragma unroll
            for (int e = 0; e < 4; ++e) acc[a][f][e] = 0.f;

    if (tid < 32) sB1[tid] = b1[tid];

    if (live) {
        for (int t = tid; t < 8 * 64; t += 256) {
            int r = t >> 6, q = t & 63;
            *(float4*)(sXi + r * XSTR + q * 4) = ((const float4*)(Xb + (size_t)(i0 + r) * DIM))[q];
        }
        for (int t = tid; t < 32 * 64; t += 256) {
            int r = t >> 6, q = t & 63;
            *(float4*)(sXj + r * XSTR + q * 4) = ((const float4*)(Xb + (size_t)(j0 + r) * DIM))[q];
        }
        __syncthreads();

        const float* xiw = sXi + w * XSTR;
        const float2* wfb = (const float2*)g_wf + lane;

        #pragma unroll 2
        for (int kb = 0; kb < 32; ++kb) {
            const int d0 = kb * 8;
            const float2* wf = wfb + (size_t)kb * 256;
            uint32_t Bm[4][2], Bs[4][2];
            #pragma unroll
            for (int f = 0; f < 4; ++f) {
                float2 v0 = __ldg(wf + f * 32);
                float2 v1 = __ldg(wf + 128 + f * 32);
                Bm[f][0] = __float_as_uint(v0.x); Bm[f][1] = __float_as_uint(v0.y);
                Bs[f][0] = __float_as_uint(v1.x); Bs[f][1] = __float_as_uint(v1.y);
            }
            const float xi0 = xiw[d0 + tq];
            const float xi1 = xiw[d0 + tq + 4];
            float xa[4], xb_[4];
            #pragma unroll
            for (int a = 0; a < 4; ++a) {
                const float* xr = sXj + (tg + a * 8) * XSTR + d0;
                xa[a] = xr[tq]; xb_[a] = xr[tq + 4];
            }
            uint32_t Am[2][4], As[2][4];
            #pragma unroll
            for (int fr = 0; fr < 2; ++fr) {
                const int r0 = fr * 2, r1 = fr * 2 + 1;
                Am[fr][0] = tf32c(xi0 * xa[r0]);
                Am[fr][1] = tf32c(xi0 * xa[r1]);
                Am[fr][2] = tf32c(xi1 * xb_[r0]);
                Am[fr][3] = tf32c(xi1 * xb_[r1]);
                As[fr][0] = tf32c(fabsf(xi0 - xa[r0]));
                As[fr][1] = tf32c(fabsf(xi0 - xa[r1]));
                As[fr][2] = tf32c(fabsf(xi1 - xb_[r0]));
                As[fr][3] = tf32c(fabsf(xi1 - xb_[r1]));
            }
            #pragma unroll
            for (int fr = 0; fr < 2; ++fr)
                #pragma unroll
                for (int f = 0; f < 4; ++f) {
                    mma_tf32(acc[fr][f], Am[fr], Bm[f]);
                    mma_tf32(acc[fr][f], As[fr], Bs[f]);
                }
        }
    } else {
        __syncthreads();    // keep barrier alignment trivial (whole CTA here)
    }

    // epilogue: bias + relu + mask -> g_h[b][i][j][:]  AND mirror g_h[b][j][i][:]
    const int gi = i0 + w;
    const bool vi = gi < plen;
    #pragma unroll
    for (int fr = 0; fr < 2; ++fr) {
        #pragma unroll
        for (int s = 0; s < 2; ++s) {
            const int gj = j0 + fr * 16 + tg + 8 * s;
            const bool v = vi && (gj < plen);
            float* Hrow = g_h + ((size_t)(b * LQ + gi) * LQ + gj) * CH;
            float* Hcol = g_h + ((size_t)(b * LQ + gj) * LQ + gi) * CH;
            #pragma unroll
            for (int f = 0; f < 4; ++f) {
                const int ch = f * 8 + 2 * tq;
                float2 val;
                val.x = v ? fmaxf(acc[fr][f][2 * s]     + sB1[ch],     0.f) : 0.f;
                val.y = v ? fmaxf(acc[fr][f][2 * s + 1] + sB1[ch + 1], 0.f) : 0.f;
                *(float2*)(Hrow + ch) = val;
                *(float2*)(Hcol + ch) = val;
            }
        }
    }
}

// ---- Kernel 2: row conv  Q[b,u,i,j] = sum_{v,c} h[b,i,j+v-3,c] * W2[u,v,c] --
#define HSTR 36
__global__ __launch_bounds__(256) void k_rowconv(const float* __restrict__ W2,
                                                 const int* __restrict__ plen_p) {
    __shared__ __align__(16) float sH[262 * HSTR];   // 37.7 KB
    __shared__ __align__(16) float sW2[49 * CH];     // 6.3 KB
    const int tid = threadIdx.x;
    const int i = blockIdx.x, b = blockIdx.y;
    const int plen = __ldg(plen_p + b);
    const int j = tid;

    // rows i >= plen: h row is exactly zero -> Q row is exactly zero.
    if (i >= plen) {
        float* Qb = g_q + (size_t)b * 7 * (LQ * LQ) + (size_t)i * LQ + j;
        #pragma unroll
        for (int u = 0; u < 7; ++u) Qb[(size_t)u * (LQ * LQ)] = 0.f;
        return;
    }

    for (int t = tid; t < 49 * CH; t += 256) sW2[t] = W2[t];
    const float* Hrow = g_h + ((size_t)(b * LQ + i) * LQ) * CH;
    for (int idx = tid; idx < 262 * 8; idx += 256) {
        int p = idx >> 3, q = idx & 7;                 // pixel p = gj + 3
        int gj = p - 3;
        float4 v = (gj >= 0 && gj < LQ) ? ((const float4*)(Hrow + (size_t)gj * CH))[q]
                                        : make_float4(0.f, 0.f, 0.f, 0.f);
        *(float4*)(sH + p * HSTR + q * 4) = v;
    }
    __syncthreads();

    unsigned long long acc2[7][2];
    #pragma unroll
    for (int u = 0; u < 7; ++u) { acc2[u][0] = 0ull; acc2[u][1] = 0ull; }

    #pragma unroll
    for (int v = 0; v < 7; ++v) {
        const float* hp = sH + (j + v) * HSTR;
        unsigned long long h2[16];
        #pragma unroll
        for (int q = 0; q < 8; ++q) {
            float4 hv = *(const float4*)(hp + q * 4);
            h2[2*q] = pk2(hv.x, hv.y); h2[2*q+1] = pk2(hv.z, hv.w);
        }
        #pragma unroll
        for (int u = 0; u < 7; ++u) {
            const ulonglong2* wv = (const ulonglong2*)(sW2 + (u * 7 + v) * CH);
            #pragma unroll
            for (int k = 0; k < 8; ++k) {
                ulonglong2 wq = wv[k];
                fma2(acc2[u][0], h2[2*k],   wq.x);
                fma2(acc2[u][1], h2[2*k+1], wq.y);
            }
        }
    }
    float* Qb = g_q + (size_t)b * 7 * (LQ * LQ) + (size_t)i * LQ + j;
    #pragma unroll
    for (int u = 0; u < 7; ++u) {
        float2 fa = up2(acc2[u][0]), fb = up2(acc2[u][1]);
        Qb[(size_t)u * (LQ * LQ)] = (fa.x + fa.y) + (fb.x + fb.y);
    }
}

// ---- Kernel 3: col gather  out[b,i,j] = mask * (b2 + sum_u Q[b,u,i+u-3,j]) --
__global__ __launch_bounds__(256) void k_colgather(const int* __restrict__ plen_p,
                                                   const float* __restrict__ b2,
                                                   float* __restrict__ out) {
    const int j = threadIdx.x;
    const int i = blockIdx.x, b = blockIdx.y;
    const int plen = plen_p[b];
    const float* Qb = g_q + (size_t)b * 7 * (LQ * LQ) + j;
    float sum = 0.f;
    #pragma unroll
    for (int u = 0; u < 7; ++u) {
        int ii = i + u - 3;
        if (ii >= 0 && ii < LQ)
            sum += Qb[(size_t)u * (LQ * LQ) + (size_t)ii * LQ];
    }
    out[((size_t)b * LQ + i) * LQ + j] =
        (i < plen && j < plen) ? (sum + b2[0]) : 0.f;
}

extern "C" void kernel_launch(void* const* d_in, const int* in_sizes, int n_in,
                              void* d_out, int out_size) {
    const float* enc  = (const float*)d_in[0];
    const int*   plen = (const int*)d_in[1];
    const float* W1   = (const float*)d_in[2];
    const float* b1   = (const float*)d_in[3];
    const float* W2   = (const float*)d_in[4];
    const float* b2   = (const float*)d_in[5];
    float* out = (float*)d_out;

    k_prewf<<<64, 256>>>(W1);

    cudaFuncSetAttribute(k_pair, cudaFuncAttributeMaxDynamicSharedMemorySize, SMEM1);
    dim3 g1(NKEEP, 1, BATCH);                   // 144 upper-tri blocks x 8 batches
    k_pair<<<g1, 256, SMEM1>>>(enc, plen, b1);

    dim3 g2(LQ, BATCH);
    k_rowconv<<<g2, 256>>>(W2, plen);

    dim3 g3(LQ, BATCH);
    k_colgather<<<g3, 256>>>(plen, b2, out);
}